// round 11
// baseline (speedup 1.0000x reference)
#include <cuda_runtime.h>
#include <cuda_fp16.h>
#include <cstdint>

#define BB 4096
#define TT 512
#define IND 64
#define HH 10

// 335.5 MB scratch: permuted layout idx = bt*40 + g', g' = j*4+gate (0=i 1=f 2=g 3=o)
__device__ float xg_buf[(size_t)BB * TT * 40];

// Pre-split, pre-permuted, pre-swizzled W halves: chunk of k XORed with (g'&7)
__device__ half whg[2 * 40 * 64];
// Pre-summed biases in permuted order
__device__ float bsumg[40];

__device__ __forceinline__ void fma2(unsigned long long& d,
                                     unsigned long long a,
                                     unsigned long long b) {
    asm("fma.rn.f32x2 %0, %1, %2, %0;" : "+l"(d) : "l"(a), "l"(b));
}
#define PACK2(d, lo, hi) \
    asm("mov.b64 %0, {%1, %2};" : "=l"(d) : "f"(lo), "f"(hi))
#define UNPACK2(lo, hi, s) \
    asm("mov.b64 {%0, %1}, %2;" : "=f"(lo), "=f"(hi) : "l"(s))

// ---------------------------------------------------------------------------
// K0: prep — split W_ih into fp16 hi/lo, permute gate order, apply swizzle.
// ---------------------------------------------------------------------------
__global__ void prep_kernel(const float* __restrict__ W_ih,
                            const float* __restrict__ b_ih,
                            const float* __restrict__ b_hh)
{
    int e = blockIdx.x * 128 + threadIdx.x;
    if (e < 2560) {
        int g = e >> 6, k = e & 63;
        int gp = (g % 10) * 4 + g / 10;            // permuted column
        float v = W_ih[e];
        half hi = __float2half_rn(v);
        half lo = __float2half_rn(v - __half2float(hi));
        int kp = (((k >> 3) ^ (gp & 7)) << 3) | (k & 7);   // chunk XOR swizzle
        whg[gp * 64 + kp] = hi;
        whg[2560 + gp * 64 + kp] = lo;
    }
    if (e < 40) {
        int gp = (e % 10) * 4 + e / 10;
        bsumg[gp] = b_ih[e] + b_hh[e];
    }
}

// ---------------------------------------------------------------------------
// K1: xg = x · W_ihᵀ + bias via mma.sync m16n8k16, 2xfp16 3-pass split.
// 256 threads (8 warps x 16 rows = 128 rows/block). Fused pass loading:
// per ks load Ahi/Alo/Bhi/Blo frags once -> 15 MMAs per 28 LDS per warp.
// ---------------------------------------------------------------------------
__device__ __forceinline__ void mma16816(float* c, uint32_t a0, uint32_t a1,
                                         uint32_t a2, uint32_t a3,
                                         uint32_t b0, uint32_t b1)
{
    asm volatile(
        "mma.sync.aligned.m16n8k16.row.col.f32.f16.f16.f32 "
        "{%0,%1,%2,%3}, {%4,%5,%6,%7}, {%8,%9}, {%0,%1,%2,%3};"
        : "+f"(c[0]), "+f"(c[1]), "+f"(c[2]), "+f"(c[3])
        : "r"(a0), "r"(a1), "r"(a2), "r"(a3), "r"(b0), "r"(b1));
}

__global__ __launch_bounds__(256, 4)
void input_proj_mma(const float* __restrict__ x, int block0)
{
    __shared__ __align__(16) half Ah[128 * 64];     // 16 KB, swizzled
    __shared__ __align__(16) half Al[128 * 64];     // 16 KB
    __shared__ __align__(16) half Bsm[2 * 40 * 64]; // 10 KB (hi, lo planes)
    __shared__ __align__(8)  float bsm[40];

    const int tid  = threadIdx.x;
    const int lane = tid & 31;
    const int wid  = tid >> 5;                     // 0..7, 16 rows each
    const size_t row0 = (size_t)(blockIdx.x + block0) * 128;

    // ---- stage x: fp32 -> hi/lo fp16 planes, chunk-XOR swizzle ----
    const float4* x4 = (const float4*)(x + row0 * IND);
    #pragma unroll
    for (int u = 0; u < 4; ++u) {
        int ch = tid + u * 256;                    // 1024 chunks = 128 rows x 8
        int r = ch >> 3, c = ch & 7;
        float4 v0 = __ldcs(&x4[r * 16 + c * 2]);
        float4 v1 = __ldcs(&x4[r * 16 + c * 2 + 1]);
        float f[8] = {v0.x, v0.y, v0.z, v0.w, v1.x, v1.y, v1.z, v1.w};
        half hi8[8], lo8[8];
        #pragma unroll
        for (int i = 0; i < 8; ++i) {
            hi8[i] = __float2half_rn(f[i]);
            lo8[i] = __float2half_rn(f[i] - __half2float(hi8[i]));
        }
        int off = r * 64 + ((c ^ (r & 7)) << 3);
        *(uint4*)&Ah[off] = *(const uint4*)hi8;
        *(uint4*)&Al[off] = *(const uint4*)lo8;
    }
    // ---- stage W planes (already permuted+swizzled) + bias ----
    {
        const float4* wg4 = (const float4*)whg;    // 10240 B = 640 float4
        #pragma unroll
        for (int i = tid; i < 640; i += 256)
            ((float4*)Bsm)[i] = wg4[i];
        if (tid < 40)
            bsm[tid] = bsumg[tid];
    }
    __syncthreads();

    // ---- mma mainloop ----
    const int mrow0 = wid * 16;
    const int rgrp  = lane >> 2;                   // 0..7
    const int kq    = lane & 3;                    // 0..3
    const int ra    = mrow0 + rgrp;                // (ra&7)==rgrp

    float acc[5][4];
    #pragma unroll
    for (int n = 0; n < 5; ++n)
        #pragma unroll
        for (int i = 0; i < 4; ++i)
            acc[n][i] = 0.0f;

    #pragma unroll
    for (int ks = 0; ks < 4; ++ks) {
        const int ch0 = ((2 * ks)     ^ rgrp) * 8 + 2 * kq;
        const int ch1 = ((2 * ks + 1) ^ rgrp) * 8 + 2 * kq;

        uint32_t ah[4], al[4];
        ah[0] = *(const uint32_t*)&Ah[ra * 64 + ch0];
        ah[1] = *(const uint32_t*)&Ah[(ra + 8) * 64 + ch0];
        ah[2] = *(const uint32_t*)&Ah[ra * 64 + ch1];
        ah[3] = *(const uint32_t*)&Ah[(ra + 8) * 64 + ch1];
        al[0] = *(const uint32_t*)&Al[ra * 64 + ch0];
        al[1] = *(const uint32_t*)&Al[(ra + 8) * 64 + ch0];
        al[2] = *(const uint32_t*)&Al[ra * 64 + ch1];
        al[3] = *(const uint32_t*)&Al[(ra + 8) * 64 + ch1];

        #pragma unroll
        for (int n = 0; n < 5; ++n) {
            const int g = n * 8 + rgrp;            // (g&7)==rgrp -> same chunks
            uint32_t bh0 = *(const uint32_t*)&Bsm[g * 64 + ch0];
            uint32_t bh1 = *(const uint32_t*)&Bsm[g * 64 + ch1];
            uint32_t bl0 = *(const uint32_t*)&Bsm[2560 + g * 64 + ch0];
            uint32_t bl1 = *(const uint32_t*)&Bsm[2560 + g * 64 + ch1];
            mma16816(acc[n], ah[0], ah[1], ah[2], ah[3], bh0, bh1);
            mma16816(acc[n], ah[0], ah[1], ah[2], ah[3], bl0, bl1);
            mma16816(acc[n], al[0], al[1], al[2], al[3], bh0, bh1);
        }
    }

    // ---- epilogue: + bias, direct STG.64 (cols already permuted) ----
    const size_t grA = row0 + mrow0 + rgrp;        // D rows rgrp, rgrp+8
    #pragma unroll
    for (int n = 0; n < 5; ++n) {
        const int cn = n * 8 + 2 * kq;
        float2 bp = *(const float2*)&bsm[cn];
        float2 o0 = make_float2(acc[n][0] + bp.x, acc[n][1] + bp.y);
        float2 o1 = make_float2(acc[n][2] + bp.x, acc[n][3] + bp.y);
        __stcs((float2*)(xg_buf + grA * 40 + cn), o0);
        __stcs((float2*)(xg_buf + (grA + 8) * 40 + cn), o1);
    }
}

// ---------------------------------------------------------------------------
// K2: recurrent scan. 2 batches/warp (lanes 0..19) -> 2048 warps chip-wide
// for latency hiding. shfl h-broadcast, k-paired fma2.
// ---------------------------------------------------------------------------
__device__ __forceinline__ float sigm_fast(float x) {
    return __fdividef(1.0f, 1.0f + __expf(-x));
}
__device__ __forceinline__ float tanh_fast(float x) {
    return 1.0f - 2.0f * __fdividef(1.0f, 1.0f + __expf(2.0f * x));
}

#define K2_THREADS 128
#define K2_BATCH_PER_BLOCK 8          // 4 warps x 2 batches

__global__ __launch_bounds__(K2_THREADS, 1)
void lstm_scan_kernel(const float* __restrict__ W_hh,
                      float* __restrict__ out)
{
    const int lane = threadIdx.x & 31;
    const int warp = threadIdx.x >> 5;
    int group = lane / 10;                 // 0,1 active; clamp rest
    const bool active = (lane < 20);
    if (!active) group = 1;
    const int j = active ? (lane - group * 10) : 0;

    const int b = blockIdx.x * K2_BATCH_PER_BLOCK + warp * 2 + group;
    const bool valid = active && (b < BB);
    const int b_eff = valid ? b : 0;

    // k-paired recurrent weights: (w[2p], w[2p+1]) per gate
    unsigned long long wI2[5], wF2[5], wG2[5], wO2[5];
    #pragma unroll
    for (int p = 0; p < 5; ++p) {
        PACK2(wI2[p], W_hh[(j)      * HH + 2 * p], W_hh[(j)      * HH + 2 * p + 1]);
        PACK2(wF2[p], W_hh[(j + 10) * HH + 2 * p], W_hh[(j + 10) * HH + 2 * p + 1]);
        PACK2(wG2[p], W_hh[(j + 20) * HH + 2 * p], W_hh[(j + 20) * HH + 2 * p + 1]);
        PACK2(wO2[p], W_hh[(j + 30) * HH + 2 * p], W_hh[(j + 30) * HH + 2 * p + 1]);
    }

    const float4* xgp = (const float4*)(xg_buf + (size_t)b_eff * TT * 40) + j;

    float4 pf[8];
    #pragma unroll
    for (int d = 0; d < 8; ++d)
        pf[d] = __ldcs(&xgp[(size_t)d * 10]);

    float h = 0.0f, c = 0.0f;
    float* outp = out + (size_t)b_eff * TT * HH + j;
    const int srcbase = group * 10;

    for (int t = 0; t < TT; t += 8) {
        #pragma unroll
        for (int u = 0; u < 8; ++u) {
            float4 xv = pf[u];
            int tn = t + u + 8;
            if (tn < TT)
                pf[u] = __ldcs(&xgp[(size_t)tn * 10]);

            // gather h pairs via shfl, pack into f32x2
            unsigned long long hp[5];
            #pragma unroll
            for (int p = 0; p < 5; ++p) {
                float h0 = __shfl_sync(0xffffffffu, h, srcbase + 2 * p);
                float h1 = __shfl_sync(0xffffffffu, h, srcbase + 2 * p + 1);
                PACK2(hp[p], h0, h1);
            }

            unsigned long long aI2, aF2, aG2, aO2;
            PACK2(aI2, xv.x, 0.0f);
            PACK2(aF2, xv.y, 0.0f);
            PACK2(aG2, xv.z, 0.0f);
            PACK2(aO2, xv.w, 0.0f);
            #pragma unroll
            for (int p = 0; p < 5; ++p) {
                fma2(aI2, hp[p], wI2[p]);
                fma2(aF2, hp[p], wF2[p]);
                fma2(aG2, hp[p], wG2[p]);
                fma2(aO2, hp[p], wO2[p]);
            }
            float e0, f0, e1, f1, e2, f2, e3, f3;
            UNPACK2(e0, f0, aI2);
            UNPACK2(e1, f1, aF2);
            UNPACK2(e2, f2, aG2);
            UNPACK2(e3, f3, aO2);

            float ig = sigm_fast(e0 + f0);
            float fg = sigm_fast(e1 + f1);
            float gg = tanh_fast(e2 + f2);
            float og = sigm_fast(e3 + f3);
            c = fmaf(fg, c, ig * gg);
            h = og * tanh_fast(c);

            if (valid)
                __stcs(&outp[(size_t)(t + u) * HH], h);
        }
    }

    if (valid)
        out[(size_t)BB * TT * HH + (size_t)b * HH + j] = h;
}

// ---------------------------------------------------------------------------
extern "C" void kernel_launch(void* const* d_in, const int* in_sizes, int n_in,
                              void* d_out, int out_size)
{
    const float* x    = (const float*)d_in[0];
    const float* W_ih = (const float*)d_in[1];
    const float* W_hh = (const float*)d_in[2];
    const float* b_ih = (const float*)d_in[3];
    const float* b_hh = (const float*)d_in[4];
    float* out = (float*)d_out;

    prep_kernel<<<20, 128>>>(W_ih, b_ih, b_hh);

    // K1: 16384 CTAs of 128 rows, 5 chunks -> ncu's 6th launch is a K1 chunk
    const int total_blocks = (BB * TT) / 128;      // 16384
    const int chunk = 3277;
    int done = 0;
    for (int i = 0; i < 5; ++i) {
        int g = total_blocks - done < chunk ? total_blocks - done : chunk;
        if (g > 0)
            input_proj_mma<<<g, 256>>>(x, done);
        done += g;
    }

    int grid2 = (BB + K2_BATCH_PER_BLOCK - 1) / K2_BATCH_PER_BLOCK;  // 512
    lstm_scan_kernel<<<grid2, K2_THREADS>>>(W_hh, out);
}

// round 12
// speedup vs baseline: 1.3120x; 1.3120x over previous
#include <cuda_runtime.h>
#include <cuda_fp16.h>
#include <cstdint>

#define BB 4096
#define TT 512
#define IND 64
#define HH 10

// 335.5 MB scratch: permuted layout idx = bt*40 + g', g' = j*4+gate (0=i 1=f 2=g 3=o)
__device__ float xg_buf[(size_t)BB * TT * 40];

// Pre-split, pre-permuted, pre-swizzled W halves: chunk of k XORed with (g'&7)
__device__ half whg[2 * 40 * 64];
// Pre-summed biases in permuted order
__device__ float bsumg[40];

// ---------------------------------------------------------------------------
// K0: prep — split W_ih into fp16 hi/lo, permute gate order, apply swizzle.
// ---------------------------------------------------------------------------
__global__ void prep_kernel(const float* __restrict__ W_ih,
                            const float* __restrict__ b_ih,
                            const float* __restrict__ b_hh)
{
    int e = blockIdx.x * 128 + threadIdx.x;
    if (e < 2560) {
        int g = e >> 6, k = e & 63;
        int gp = (g % 10) * 4 + g / 10;            // permuted column
        float v = W_ih[e];
        half hi = __float2half_rn(v);
        half lo = __float2half_rn(v - __half2float(hi));
        int kp = (((k >> 3) ^ (gp & 7)) << 3) | (k & 7);   // chunk XOR swizzle
        whg[gp * 64 + kp] = hi;
        whg[2560 + gp * 64 + kp] = lo;
    }
    if (e < 40) {
        int gp = (e % 10) * 4 + e / 10;
        bsumg[gp] = b_ih[e] + b_hh[e];
    }
}

// ---------------------------------------------------------------------------
// K1: xg = x · W_ihᵀ + bias via mma.sync m16n8k16, 2xfp16 3-pass split.
// 256 threads (8 warps x 16 rows = 128 rows/block). Fused pass loading.
// (R11 version: 34.9 us/chunk, occ 44.5%)
// ---------------------------------------------------------------------------
__device__ __forceinline__ void mma16816(float* c, uint32_t a0, uint32_t a1,
                                         uint32_t a2, uint32_t a3,
                                         uint32_t b0, uint32_t b1)
{
    asm volatile(
        "mma.sync.aligned.m16n8k16.row.col.f32.f16.f16.f32 "
        "{%0,%1,%2,%3}, {%4,%5,%6,%7}, {%8,%9}, {%0,%1,%2,%3};"
        : "+f"(c[0]), "+f"(c[1]), "+f"(c[2]), "+f"(c[3])
        : "r"(a0), "r"(a1), "r"(a2), "r"(a3), "r"(b0), "r"(b1));
}

__global__ __launch_bounds__(256, 4)
void input_proj_mma(const float* __restrict__ x, int block0)
{
    __shared__ __align__(16) half Ah[128 * 64];     // 16 KB, swizzled
    __shared__ __align__(16) half Al[128 * 64];     // 16 KB
    __shared__ __align__(16) half Bsm[2 * 40 * 64]; // 10 KB (hi, lo planes)
    __shared__ __align__(8)  float bsm[40];

    const int tid  = threadIdx.x;
    const int lane = tid & 31;
    const int wid  = tid >> 5;                     // 0..7, 16 rows each
    const size_t row0 = (size_t)(blockIdx.x + block0) * 128;

    // ---- stage x: fp32 -> hi/lo fp16 planes, chunk-XOR swizzle ----
    const float4* x4 = (const float4*)(x + row0 * IND);
    #pragma unroll
    for (int u = 0; u < 4; ++u) {
        int ch = tid + u * 256;                    // 1024 chunks = 128 rows x 8
        int r = ch >> 3, c = ch & 7;
        float4 v0 = __ldcs(&x4[r * 16 + c * 2]);
        float4 v1 = __ldcs(&x4[r * 16 + c * 2 + 1]);
        float f[8] = {v0.x, v0.y, v0.z, v0.w, v1.x, v1.y, v1.z, v1.w};
        half hi8[8], lo8[8];
        #pragma unroll
        for (int i = 0; i < 8; ++i) {
            hi8[i] = __float2half_rn(f[i]);
            lo8[i] = __float2half_rn(f[i] - __half2float(hi8[i]));
        }
        int off = r * 64 + ((c ^ (r & 7)) << 3);
        *(uint4*)&Ah[off] = *(const uint4*)hi8;
        *(uint4*)&Al[off] = *(const uint4*)lo8;
    }
    // ---- stage W planes (already permuted+swizzled) + bias ----
    {
        const float4* wg4 = (const float4*)whg;    // 10240 B = 640 float4
        #pragma unroll
        for (int i = tid; i < 640; i += 256)
            ((float4*)Bsm)[i] = wg4[i];
        if (tid < 40)
            bsm[tid] = bsumg[tid];
    }
    __syncthreads();

    // ---- mma mainloop ----
    const int mrow0 = wid * 16;
    const int rgrp  = lane >> 2;                   // 0..7
    const int kq    = lane & 3;                    // 0..3
    const int ra    = mrow0 + rgrp;                // (ra&7)==rgrp

    float acc[5][4];
    #pragma unroll
    for (int n = 0; n < 5; ++n)
        #pragma unroll
        for (int i = 0; i < 4; ++i)
            acc[n][i] = 0.0f;

    #pragma unroll
    for (int ks = 0; ks < 4; ++ks) {
        const int ch0 = ((2 * ks)     ^ rgrp) * 8 + 2 * kq;
        const int ch1 = ((2 * ks + 1) ^ rgrp) * 8 + 2 * kq;

        uint32_t ah[4], al[4];
        ah[0] = *(const uint32_t*)&Ah[ra * 64 + ch0];
        ah[1] = *(const uint32_t*)&Ah[(ra + 8) * 64 + ch0];
        ah[2] = *(const uint32_t*)&Ah[ra * 64 + ch1];
        ah[3] = *(const uint32_t*)&Ah[(ra + 8) * 64 + ch1];
        al[0] = *(const uint32_t*)&Al[ra * 64 + ch0];
        al[1] = *(const uint32_t*)&Al[(ra + 8) * 64 + ch0];
        al[2] = *(const uint32_t*)&Al[ra * 64 + ch1];
        al[3] = *(const uint32_t*)&Al[(ra + 8) * 64 + ch1];

        #pragma unroll
        for (int n = 0; n < 5; ++n) {
            const int g = n * 8 + rgrp;            // (g&7)==rgrp -> same chunks
            uint32_t bh0 = *(const uint32_t*)&Bsm[g * 64 + ch0];
            uint32_t bh1 = *(const uint32_t*)&Bsm[g * 64 + ch1];
            uint32_t bl0 = *(const uint32_t*)&Bsm[2560 + g * 64 + ch0];
            uint32_t bl1 = *(const uint32_t*)&Bsm[2560 + g * 64 + ch1];
            mma16816(acc[n], ah[0], ah[1], ah[2], ah[3], bh0, bh1);
            mma16816(acc[n], ah[0], ah[1], ah[2], ah[3], bl0, bl1);
            mma16816(acc[n], al[0], al[1], al[2], al[3], bh0, bh1);
        }
    }

    // ---- epilogue: + bias, direct STG.64 (cols already permuted) ----
    const size_t grA = row0 + mrow0 + rgrp;        // D rows rgrp, rgrp+8
    #pragma unroll
    for (int n = 0; n < 5; ++n) {
        const int cn = n * 8 + 2 * kq;
        float2 bp = *(const float2*)&bsm[cn];
        float2 o0 = make_float2(acc[n][0] + bp.x, acc[n][1] + bp.y);
        float2 o1 = make_float2(acc[n][2] + bp.x, acc[n][3] + bp.y);
        __stcs((float2*)(xg_buf + grA * 40 + cn), o0);
        __stcs((float2*)(xg_buf + (grA + 8) * 40 + cn), o1);
    }
}

// ---------------------------------------------------------------------------
// K2: recurrent scan — exact R9 version (measured ~119 us, the best so far).
// 3 batches/warp (lanes 0..29), unit j = lane%10, h broadcast via shfl.
// ---------------------------------------------------------------------------
__device__ __forceinline__ float sigm_fast(float x) {
    return __fdividef(1.0f, 1.0f + __expf(-x));
}
__device__ __forceinline__ float tanh_fast(float x) {
    return 1.0f - 2.0f * __fdividef(1.0f, 1.0f + __expf(2.0f * x));
}

#define K2_THREADS 64
#define K2_BATCH_PER_BLOCK 6

__global__ __launch_bounds__(K2_THREADS, 1)
void lstm_scan_kernel(const float* __restrict__ W_hh,
                      float* __restrict__ out)
{
    const int lane = threadIdx.x & 31;
    const int warp = threadIdx.x >> 5;
    int group = lane / 10;
    const bool active = (lane < 30);
    if (!active) group = 2;
    const int j = active ? (lane - group * 10) : 0;

    const int b = blockIdx.x * K2_BATCH_PER_BLOCK + warp * 3 + group;
    const bool valid = active && (b < BB);
    const int b_eff = valid ? b : 0;

    float wI[10], wF[10], wG[10], wO[10];
    #pragma unroll
    for (int k = 0; k < 10; ++k) {
        wI[k] = W_hh[(j)      * HH + k];
        wF[k] = W_hh[(j + 10) * HH + k];
        wG[k] = W_hh[(j + 20) * HH + k];
        wO[k] = W_hh[(j + 30) * HH + k];
    }

    const float4* xgp = (const float4*)(xg_buf + (size_t)b_eff * TT * 40) + j;

    float4 pf[8];
    #pragma unroll
    for (int d = 0; d < 8; ++d)
        pf[d] = __ldcs(&xgp[(size_t)d * 10]);

    float h = 0.0f, c = 0.0f;
    float* outp = out + (size_t)b_eff * TT * HH + j;
    const int srcbase = group * 10;

    for (int t = 0; t < TT; t += 8) {
        #pragma unroll
        for (int u = 0; u < 8; ++u) {
            float4 xv = pf[u];
            int tn = t + u + 8;
            if (tn < TT)
                pf[u] = __ldcs(&xgp[(size_t)tn * 10]);

            float aI = xv.x, aF = xv.y, aG = xv.z, aO = xv.w;
            #pragma unroll
            for (int k = 0; k < 10; ++k) {
                float hk = __shfl_sync(0xffffffffu, h, srcbase + k);
                aI = fmaf(hk, wI[k], aI);
                aF = fmaf(hk, wF[k], aF);
                aG = fmaf(hk, wG[k], aG);
                aO = fmaf(hk, wO[k], aO);
            }
            float ig = sigm_fast(aI);
            float fg = sigm_fast(aF);
            float gg = tanh_fast(aG);
            float og = sigm_fast(aO);
            c = fmaf(fg, c, ig * gg);
            h = og * tanh_fast(c);

            if (valid)
                __stcs(&outp[(size_t)(t + u) * HH], h);
        }
    }

    if (valid)
        out[(size_t)BB * TT * HH + (size_t)b * HH + j] = h;
}

// ---------------------------------------------------------------------------
extern "C" void kernel_launch(void* const* d_in, const int* in_sizes, int n_in,
                              void* d_out, int out_size)
{
    const float* x    = (const float*)d_in[0];
    const float* W_ih = (const float*)d_in[1];
    const float* W_hh = (const float*)d_in[2];
    const float* b_ih = (const float*)d_in[3];
    const float* b_hh = (const float*)d_in[4];
    float* out = (float*)d_out;

    prep_kernel<<<20, 128>>>(W_ih, b_ih, b_hh);

    // K1: 16384 CTAs of 128 rows, 5 chunks -> ncu's 6th launch is a K1 chunk
    const int total_blocks = (BB * TT) / 128;      // 16384
    const int chunk = 3277;
    int done = 0;
    for (int i = 0; i < 5; ++i) {
        int g = total_blocks - done < chunk ? total_blocks - done : chunk;
        if (g > 0)
            input_proj_mma<<<g, 256>>>(x, done);
        done += g;
    }

    int grid2 = (BB + K2_BATCH_PER_BLOCK - 1) / K2_BATCH_PER_BLOCK;  // 683
    lstm_scan_kernel<<<grid2, K2_THREADS>>>(W_hh, out);
}

// round 13
// speedup vs baseline: 1.3769x; 1.0495x over previous
#include <cuda_runtime.h>
#include <cuda_fp16.h>
#include <cstdint>

#define BB 4096
#define TT 512
#define IND 64
#define HH 10

// 168 MB fp16 scratch: per bt, 20 half2 = 40 halves, idx = j*4+gate (i,f,g,o)
__device__ __half2 xg_h[(size_t)BB * TT * 20];

// Pre-split, pre-permuted, pre-swizzled W halves: chunk of k XORed with (g'&7)
__device__ half whg[2 * 40 * 64];
// Pre-summed biases in permuted order
__device__ float bsumg[40];

// ---------------------------------------------------------------------------
// K0: prep — split W_ih into fp16 hi/lo, permute gate order, apply swizzle.
// ---------------------------------------------------------------------------
__global__ void prep_kernel(const float* __restrict__ W_ih,
                            const float* __restrict__ b_ih,
                            const float* __restrict__ b_hh)
{
    int e = blockIdx.x * 128 + threadIdx.x;
    if (e < 2560) {
        int g = e >> 6, k = e & 63;
        int gp = (g % 10) * 4 + g / 10;            // permuted column
        float v = W_ih[e];
        half hi = __float2half_rn(v);
        half lo = __float2half_rn(v - __half2float(hi));
        int kp = (((k >> 3) ^ (gp & 7)) << 3) | (k & 7);   // chunk XOR swizzle
        whg[gp * 64 + kp] = hi;
        whg[2560 + gp * 64 + kp] = lo;
    }
    if (e < 40) {
        int gp = (e % 10) * 4 + e / 10;
        bsumg[gp] = b_ih[e] + b_hh[e];
    }
}

// ---------------------------------------------------------------------------
// K1: xg = x · W_ihᵀ + bias via mma.sync m16n8k16, 2xfp16 3-pass split.
// 256 threads (8 warps x 16 rows = 128 rows/block). Fused pass loading.
// Epilogue now converts to fp16 (halves store traffic + K2 load traffic).
// ---------------------------------------------------------------------------
__device__ __forceinline__ void mma16816(float* c, uint32_t a0, uint32_t a1,
                                         uint32_t a2, uint32_t a3,
                                         uint32_t b0, uint32_t b1)
{
    asm volatile(
        "mma.sync.aligned.m16n8k16.row.col.f32.f16.f16.f32 "
        "{%0,%1,%2,%3}, {%4,%5,%6,%7}, {%8,%9}, {%0,%1,%2,%3};"
        : "+f"(c[0]), "+f"(c[1]), "+f"(c[2]), "+f"(c[3])
        : "r"(a0), "r"(a1), "r"(a2), "r"(a3), "r"(b0), "r"(b1));
}

__global__ __launch_bounds__(256, 4)
void input_proj_mma(const float* __restrict__ x, int block0)
{
    __shared__ __align__(16) half Ah[128 * 64];     // 16 KB, swizzled
    __shared__ __align__(16) half Al[128 * 64];     // 16 KB
    __shared__ __align__(16) half Bsm[2 * 40 * 64]; // 10 KB (hi, lo planes)
    __shared__ __align__(8)  float bsm[40];

    const int tid  = threadIdx.x;
    const int lane = tid & 31;
    const int wid  = tid >> 5;                     // 0..7, 16 rows each
    const size_t row0 = (size_t)(blockIdx.x + block0) * 128;

    // ---- stage x: fp32 -> hi/lo fp16 planes, chunk-XOR swizzle ----
    const float4* x4 = (const float4*)(x + row0 * IND);
    #pragma unroll
    for (int u = 0; u < 4; ++u) {
        int ch = tid + u * 256;                    // 1024 chunks = 128 rows x 8
        int r = ch >> 3, c = ch & 7;
        float4 v0 = __ldcs(&x4[r * 16 + c * 2]);
        float4 v1 = __ldcs(&x4[r * 16 + c * 2 + 1]);
        float f[8] = {v0.x, v0.y, v0.z, v0.w, v1.x, v1.y, v1.z, v1.w};
        half hi8[8], lo8[8];
        #pragma unroll
        for (int i = 0; i < 8; ++i) {
            hi8[i] = __float2half_rn(f[i]);
            lo8[i] = __float2half_rn(f[i] - __half2float(hi8[i]));
        }
        int off = r * 64 + ((c ^ (r & 7)) << 3);
        *(uint4*)&Ah[off] = *(const uint4*)hi8;
        *(uint4*)&Al[off] = *(const uint4*)lo8;
    }
    // ---- stage W planes (already permuted+swizzled) + bias ----
    {
        const float4* wg4 = (const float4*)whg;    // 10240 B = 640 float4
        #pragma unroll
        for (int i = tid; i < 640; i += 256)
            ((float4*)Bsm)[i] = wg4[i];
        if (tid < 40)
            bsm[tid] = bsumg[tid];
    }
    __syncthreads();

    // ---- mma mainloop ----
    const int mrow0 = wid * 16;
    const int rgrp  = lane >> 2;                   // 0..7
    const int kq    = lane & 3;                    // 0..3
    const int ra    = mrow0 + rgrp;                // (ra&7)==rgrp

    float acc[5][4];
    #pragma unroll
    for (int n = 0; n < 5; ++n)
        #pragma unroll
        for (int i = 0; i < 4; ++i)
            acc[n][i] = 0.0f;

    #pragma unroll
    for (int ks = 0; ks < 4; ++ks) {
        const int ch0 = ((2 * ks)     ^ rgrp) * 8 + 2 * kq;
        const int ch1 = ((2 * ks + 1) ^ rgrp) * 8 + 2 * kq;

        uint32_t ah[4], al[4];
        ah[0] = *(const uint32_t*)&Ah[ra * 64 + ch0];
        ah[1] = *(const uint32_t*)&Ah[(ra + 8) * 64 + ch0];
        ah[2] = *(const uint32_t*)&Ah[ra * 64 + ch1];
        ah[3] = *(const uint32_t*)&Ah[(ra + 8) * 64 + ch1];
        al[0] = *(const uint32_t*)&Al[ra * 64 + ch0];
        al[1] = *(const uint32_t*)&Al[(ra + 8) * 64 + ch0];
        al[2] = *(const uint32_t*)&Al[ra * 64 + ch1];
        al[3] = *(const uint32_t*)&Al[(ra + 8) * 64 + ch1];

        #pragma unroll
        for (int n = 0; n < 5; ++n) {
            const int g = n * 8 + rgrp;            // (g&7)==rgrp -> same chunks
            uint32_t bh0 = *(const uint32_t*)&Bsm[g * 64 + ch0];
            uint32_t bh1 = *(const uint32_t*)&Bsm[g * 64 + ch1];
            uint32_t bl0 = *(const uint32_t*)&Bsm[2560 + g * 64 + ch0];
            uint32_t bl1 = *(const uint32_t*)&Bsm[2560 + g * 64 + ch1];
            mma16816(acc[n], ah[0], ah[1], ah[2], ah[3], bh0, bh1);
            mma16816(acc[n], ah[0], ah[1], ah[2], ah[3], bl0, bl1);
            mma16816(acc[n], al[0], al[1], al[2], al[3], bh0, bh1);
        }
    }

    // ---- epilogue: + bias (fp32), convert to fp16, direct STG.32 ----
    const size_t grA = row0 + mrow0 + rgrp;        // D rows rgrp, rgrp+8
    #pragma unroll
    for (int n = 0; n < 5; ++n) {
        const int cn = n * 8 + 2 * kq;             // even half-index
        float2 bp = *(const float2*)&bsm[cn];
        __half2 o0 = __floats2half2_rn(acc[n][0] + bp.x, acc[n][1] + bp.y);
        __half2 o1 = __floats2half2_rn(acc[n][2] + bp.x, acc[n][3] + bp.y);
        __stcs(&xg_h[grA * 20 + (cn >> 1)], o0);
        __stcs(&xg_h[(grA + 8) * 20 + (cn >> 1)], o1);
    }
}

// ---------------------------------------------------------------------------
// K2: recurrent scan (R9 structure). 3 batches/warp, shfl h-broadcast.
// xg now fp16: 8B load + 2 cvt per step instead of 16B load.
// ---------------------------------------------------------------------------
__device__ __forceinline__ float sigm_fast(float x) {
    return __fdividef(1.0f, 1.0f + __expf(-x));
}
__device__ __forceinline__ float tanh_fast(float x) {
    return 1.0f - 2.0f * __fdividef(1.0f, 1.0f + __expf(2.0f * x));
}

#define K2_THREADS 64
#define K2_BATCH_PER_BLOCK 6

__global__ __launch_bounds__(K2_THREADS, 1)
void lstm_scan_kernel(const float* __restrict__ W_hh,
                      float* __restrict__ out)
{
    const int lane = threadIdx.x & 31;
    const int warp = threadIdx.x >> 5;
    int group = lane / 10;
    const bool active = (lane < 30);
    if (!active) group = 2;
    const int j = active ? (lane - group * 10) : 0;

    const int b = blockIdx.x * K2_BATCH_PER_BLOCK + warp * 3 + group;
    const bool valid = active && (b < BB);
    const int b_eff = valid ? b : 0;

    float wI[10], wF[10], wG[10], wO[10];
    #pragma unroll
    for (int k = 0; k < 10; ++k) {
        wI[k] = W_hh[(j)      * HH + k];
        wF[k] = W_hh[(j + 10) * HH + k];
        wG[k] = W_hh[(j + 20) * HH + k];
        wO[k] = W_hh[(j + 30) * HH + k];
    }

    // fp16 xg stream: one uint2 (4 halves: i,f,g,o) per step, stride 10 uint2
    const uint2* xgp = (const uint2*)xg_h + (size_t)b_eff * TT * 10 + j;

    uint2 pf[8];
    #pragma unroll
    for (int d = 0; d < 8; ++d)
        pf[d] = __ldcs(&xgp[(size_t)d * 10]);

    float h = 0.0f, c = 0.0f;
    float* outp = out + (size_t)b_eff * TT * HH + j;
    const int srcbase = group * 10;

    for (int t = 0; t < TT; t += 8) {
        #pragma unroll
        for (int u = 0; u < 8; ++u) {
            uint2 xv = pf[u];
            int tn = t + u + 8;
            if (tn < TT)
                pf[u] = __ldcs(&xgp[(size_t)tn * 10]);

            float2 fIF = __half22float2(*(const __half2*)&xv.x);  // i, f
            float2 fGO = __half22float2(*(const __half2*)&xv.y);  // g, o
            float aI = fIF.x, aF = fIF.y, aG = fGO.x, aO = fGO.y;
            #pragma unroll
            for (int k = 0; k < 10; ++k) {
                float hk = __shfl_sync(0xffffffffu, h, srcbase + k);
                aI = fmaf(hk, wI[k], aI);
                aF = fmaf(hk, wF[k], aF);
                aG = fmaf(hk, wG[k], aG);
                aO = fmaf(hk, wO[k], aO);
            }
            float ig = sigm_fast(aI);
            float fg = sigm_fast(aF);
            float gg = tanh_fast(aG);
            float og = sigm_fast(aO);
            c = fmaf(fg, c, ig * gg);
            h = og * tanh_fast(c);

            if (valid)
                __stcs(&outp[(size_t)(t + u) * HH], h);
        }
    }

    if (valid)
        out[(size_t)BB * TT * HH + (size_t)b * HH + j] = h;
}

// ---------------------------------------------------------------------------
extern "C" void kernel_launch(void* const* d_in, const int* in_sizes, int n_in,
                              void* d_out, int out_size)
{
    const float* x    = (const float*)d_in[0];
    const float* W_ih = (const float*)d_in[1];
    const float* W_hh = (const float*)d_in[2];
    const float* b_ih = (const float*)d_in[3];
    const float* b_hh = (const float*)d_in[4];
    float* out = (float*)d_out;

    prep_kernel<<<20, 128>>>(W_ih, b_ih, b_hh);

    // K1: 16384 CTAs of 128 rows, 5 chunks -> ncu's 6th launch is a K1 chunk
    const int total_blocks = (BB * TT) / 128;      // 16384
    const int chunk = 3277;
    int done = 0;
    for (int i = 0; i < 5; ++i) {
        int g = total_blocks - done < chunk ? total_blocks - done : chunk;
        if (g > 0)
            input_proj_mma<<<g, 256>>>(x, done);
        done += g;
    }

    int grid2 = (BB + K2_BATCH_PER_BLOCK - 1) / K2_BATCH_PER_BLOCK;  // 683
    lstm_scan_kernel<<<grid2, K2_THREADS>>>(W_hh, out);
}

// round 14
// speedup vs baseline: 1.4379x; 1.0443x over previous
#include <cuda_runtime.h>
#include <cuda_fp16.h>
#include <cstdint>

#define BB 4096
#define TT 512
#define IND 64
#define HH 10

// 168 MB fp16 scratch: per bt, 20 half2 = 40 halves, idx = j*4+gate (i,f,g,o)
__device__ __half2 xg_h[(size_t)BB * TT * 20];

// Pre-split, pre-permuted, pre-swizzled W halves: chunk of k XORed with (g'&7)
__device__ half whg[2 * 40 * 64];
// Pre-summed biases in permuted order
__device__ float bsumg[40];

// ---------------------------------------------------------------------------
// K0: prep — split W_ih into fp16 hi/lo, permute gate order, apply swizzle.
// ---------------------------------------------------------------------------
__global__ void prep_kernel(const float* __restrict__ W_ih,
                            const float* __restrict__ b_ih,
                            const float* __restrict__ b_hh)
{
    int e = blockIdx.x * 128 + threadIdx.x;
    if (e < 2560) {
        int g = e >> 6, k = e & 63;
        int gp = (g % 10) * 4 + g / 10;            // permuted column
        float v = W_ih[e];
        half hi = __float2half_rn(v);
        half lo = __float2half_rn(v - __half2float(hi));
        int kp = (((k >> 3) ^ (gp & 7)) << 3) | (k & 7);   // chunk XOR swizzle
        whg[gp * 64 + kp] = hi;
        whg[2560 + gp * 64 + kp] = lo;
    }
    if (e < 40) {
        int gp = (e % 10) * 4 + e / 10;
        bsumg[gp] = b_ih[e] + b_hh[e];
    }
}

// ---------------------------------------------------------------------------
// K1: xg = x · W_ihᵀ + bias via mma.sync m16n8k16, 2xfp16 3-pass split.
// 256 threads (8 warps x 16 rows = 128 rows/block). Fused pass loading.
// fp16 epilogue. (R13 version: 32.6 us/chunk)
// ---------------------------------------------------------------------------
__device__ __forceinline__ void mma16816(float* c, uint32_t a0, uint32_t a1,
                                         uint32_t a2, uint32_t a3,
                                         uint32_t b0, uint32_t b1)
{
    asm volatile(
        "mma.sync.aligned.m16n8k16.row.col.f32.f16.f16.f32 "
        "{%0,%1,%2,%3}, {%4,%5,%6,%7}, {%8,%9}, {%0,%1,%2,%3};"
        : "+f"(c[0]), "+f"(c[1]), "+f"(c[2]), "+f"(c[3])
        : "r"(a0), "r"(a1), "r"(a2), "r"(a3), "r"(b0), "r"(b1));
}

__global__ __launch_bounds__(256, 4)
void input_proj_mma(const float* __restrict__ x, int block0)
{
    __shared__ __align__(16) half Ah[128 * 64];     // 16 KB, swizzled
    __shared__ __align__(16) half Al[128 * 64];     // 16 KB
    __shared__ __align__(16) half Bsm[2 * 40 * 64]; // 10 KB (hi, lo planes)
    __shared__ __align__(8)  float bsm[40];

    const int tid  = threadIdx.x;
    const int lane = tid & 31;
    const int wid  = tid >> 5;                     // 0..7, 16 rows each
    const size_t row0 = (size_t)(blockIdx.x + block0) * 128;

    // ---- stage x: fp32 -> hi/lo fp16 planes, chunk-XOR swizzle ----
    const float4* x4 = (const float4*)(x + row0 * IND);
    #pragma unroll
    for (int u = 0; u < 4; ++u) {
        int ch = tid + u * 256;                    // 1024 chunks = 128 rows x 8
        int r = ch >> 3, c = ch & 7;
        float4 v0 = __ldcs(&x4[r * 16 + c * 2]);
        float4 v1 = __ldcs(&x4[r * 16 + c * 2 + 1]);
        float f[8] = {v0.x, v0.y, v0.z, v0.w, v1.x, v1.y, v1.z, v1.w};
        half hi8[8], lo8[8];
        #pragma unroll
        for (int i = 0; i < 8; ++i) {
            hi8[i] = __float2half_rn(f[i]);
            lo8[i] = __float2half_rn(f[i] - __half2float(hi8[i]));
        }
        int off = r * 64 + ((c ^ (r & 7)) << 3);
        *(uint4*)&Ah[off] = *(const uint4*)hi8;
        *(uint4*)&Al[off] = *(const uint4*)lo8;
    }
    // ---- stage W planes (already permuted+swizzled) + bias ----
    {
        const float4* wg4 = (const float4*)whg;    // 10240 B = 640 float4
        #pragma unroll
        for (int i = tid; i < 640; i += 256)
            ((float4*)Bsm)[i] = wg4[i];
        if (tid < 40)
            bsm[tid] = bsumg[tid];
    }
    __syncthreads();

    // ---- mma mainloop ----
    const int mrow0 = wid * 16;
    const int rgrp  = lane >> 2;                   // 0..7
    const int kq    = lane & 3;                    // 0..3
    const int ra    = mrow0 + rgrp;                // (ra&7)==rgrp

    float acc[5][4];
    #pragma unroll
    for (int n = 0; n < 5; ++n)
        #pragma unroll
        for (int i = 0; i < 4; ++i)
            acc[n][i] = 0.0f;

    #pragma unroll
    for (int ks = 0; ks < 4; ++ks) {
        const int ch0 = ((2 * ks)     ^ rgrp) * 8 + 2 * kq;
        const int ch1 = ((2 * ks + 1) ^ rgrp) * 8 + 2 * kq;

        uint32_t ah[4], al[4];
        ah[0] = *(const uint32_t*)&Ah[ra * 64 + ch0];
        ah[1] = *(const uint32_t*)&Ah[(ra + 8) * 64 + ch0];
        ah[2] = *(const uint32_t*)&Ah[ra * 64 + ch1];
        ah[3] = *(const uint32_t*)&Ah[(ra + 8) * 64 + ch1];
        al[0] = *(const uint32_t*)&Al[ra * 64 + ch0];
        al[1] = *(const uint32_t*)&Al[(ra + 8) * 64 + ch0];
        al[2] = *(const uint32_t*)&Al[ra * 64 + ch1];
        al[3] = *(const uint32_t*)&Al[(ra + 8) * 64 + ch1];

        #pragma unroll
        for (int n = 0; n < 5; ++n) {
            const int g = n * 8 + rgrp;            // (g&7)==rgrp -> same chunks
            uint32_t bh0 = *(const uint32_t*)&Bsm[g * 64 + ch0];
            uint32_t bh1 = *(const uint32_t*)&Bsm[g * 64 + ch1];
            uint32_t bl0 = *(const uint32_t*)&Bsm[2560 + g * 64 + ch0];
            uint32_t bl1 = *(const uint32_t*)&Bsm[2560 + g * 64 + ch1];
            mma16816(acc[n], ah[0], ah[1], ah[2], ah[3], bh0, bh1);
            mma16816(acc[n], ah[0], ah[1], ah[2], ah[3], bl0, bl1);
            mma16816(acc[n], al[0], al[1], al[2], al[3], bh0, bh1);
        }
    }

    // ---- epilogue: + bias (fp32), convert to fp16, direct STG.32 ----
    const size_t grA = row0 + mrow0 + rgrp;        // D rows rgrp, rgrp+8
    #pragma unroll
    for (int n = 0; n < 5; ++n) {
        const int cn = n * 8 + 2 * kq;             // even half-index
        float2 bp = *(const float2*)&bsm[cn];
        __half2 o0 = __floats2half2_rn(acc[n][0] + bp.x, acc[n][1] + bp.y);
        __half2 o1 = __floats2half2_rn(acc[n][2] + bp.x, acc[n][3] + bp.y);
        __stcs(&xg_h[grA * 20 + (cn >> 1)], o0);
        __stcs(&xg_h[(grA + 8) * 20 + (cn >> 1)], o1);
    }
}

// ---------------------------------------------------------------------------
// K2: recurrent scan. 3 batches/warp, shfl h-broadcast, fp16 xg stream.
// Sigmoids via single-MUFU tanh.approx identity; precise tanh for g and c.
// ---------------------------------------------------------------------------
__device__ __forceinline__ float sigm_mufu(float x) {
    // sigma(x) = 0.5*tanh(x/2) + 0.5  (FMUL + MUFU.TANH + FFMA, 1 MUFU)
    float t;
    asm("tanh.approx.f32 %0, %1;" : "=f"(t) : "f"(x * 0.5f));
    return fmaf(t, 0.5f, 0.5f);
}
__device__ __forceinline__ float tanh_fast(float x) {
    // precise-ish: 1 - 2/(e^{2x}+1)  (2 MUFU)
    return 1.0f - 2.0f * __fdividef(1.0f, 1.0f + __expf(2.0f * x));
}

#define K2_THREADS 64
#define K2_BATCH_PER_BLOCK 6

__global__ __launch_bounds__(K2_THREADS, 1)
void lstm_scan_kernel(const float* __restrict__ W_hh,
                      float* __restrict__ out)
{
    const int lane = threadIdx.x & 31;
    const int warp = threadIdx.x >> 5;
    int group = lane / 10;
    const bool active = (lane < 30);
    if (!active) group = 2;
    const int j = active ? (lane - group * 10) : 0;

    const int b = blockIdx.x * K2_BATCH_PER_BLOCK + warp * 3 + group;
    const bool valid = active && (b < BB);
    const int b_eff = valid ? b : 0;

    float wI[10], wF[10], wG[10], wO[10];
    #pragma unroll
    for (int k = 0; k < 10; ++k) {
        wI[k] = W_hh[(j)      * HH + k];
        wF[k] = W_hh[(j + 10) * HH + k];
        wG[k] = W_hh[(j + 20) * HH + k];
        wO[k] = W_hh[(j + 30) * HH + k];
    }

    // fp16 xg stream: one uint2 (4 halves: i,f,g,o) per step, stride 10 uint2
    const uint2* xgp = (const uint2*)xg_h + (size_t)b_eff * TT * 10 + j;

    uint2 pf[8];
    #pragma unroll
    for (int d = 0; d < 8; ++d)
        pf[d] = __ldcs(&xgp[(size_t)d * 10]);

    float h = 0.0f, c = 0.0f;
    float* outp = out + (size_t)b_eff * TT * HH + j;
    const int srcbase = group * 10;

    for (int t = 0; t < TT; t += 8) {
        #pragma unroll
        for (int u = 0; u < 8; ++u) {
            uint2 xv = pf[u];
            int tn = t + u + 8;
            if (tn < TT)
                pf[u] = __ldcs(&xgp[(size_t)tn * 10]);

            float2 fIF = __half22float2(*(const __half2*)&xv.x);  // i, f
            float2 fGO = __half22float2(*(const __half2*)&xv.y);  // g, o
            float aI = fIF.x, aF = fIF.y, aG = fGO.x, aO = fGO.y;
            #pragma unroll
            for (int k = 0; k < 10; ++k) {
                float hk = __shfl_sync(0xffffffffu, h, srcbase + k);
                aI = fmaf(hk, wI[k], aI);
                aF = fmaf(hk, wF[k], aF);
                aG = fmaf(hk, wG[k], aG);
                aO = fmaf(hk, wO[k], aO);
            }
            float ig = sigm_mufu(aI);
            float fg = sigm_mufu(aF);
            float gg = tanh_fast(aG);
            float og = sigm_mufu(aO);
            c = fmaf(fg, c, ig * gg);
            h = og * tanh_fast(c);

            if (valid)
                __stcs(&outp[(size_t)(t + u) * HH], h);
        }
    }

    if (valid)
        out[(size_t)BB * TT * HH + (size_t)b * HH + j] = h;
}

// ---------------------------------------------------------------------------
extern "C" void kernel_launch(void* const* d_in, const int* in_sizes, int n_in,
                              void* d_out, int out_size)
{
    const float* x    = (const float*)d_in[0];
    const float* W_ih = (const float*)d_in[1];
    const float* W_hh = (const float*)d_in[2];
    const float* b_ih = (const float*)d_in[3];
    const float* b_hh = (const float*)d_in[4];
    float* out = (float*)d_out;

    prep_kernel<<<20, 128>>>(W_ih, b_ih, b_hh);

    // K1: 16384 CTAs of 128 rows, 4 chunks -> launches 2-5; the 6th launch
    // (ncu capture window) is now K2, which we've never profiled.
    const int total_blocks = (BB * TT) / 128;      // 16384
    const int chunk = total_blocks / 4;            // 4096
    for (int i = 0; i < 4; ++i)
        input_proj_mma<<<chunk, 256>>>(x, i * chunk);

    int grid2 = (BB + K2_BATCH_PER_BLOCK - 1) / K2_BATCH_PER_BLOCK;  // 683
    lstm_scan_kernel<<<grid2, K2_THREADS>>>(W_hh, out);
}

// round 15
// speedup vs baseline: 1.6568x; 1.1522x over previous
#include <cuda_runtime.h>
#include <cuda_fp16.h>
#include <cstdint>

#define BB 4096
#define TT 512
#define IND 64
#define HH 10

// 168 MB fp16 scratch: per bt, 20 half2 = 40 halves, idx = j*4+gate (i,f,g,o)
__device__ __half2 xg_h[(size_t)BB * TT * 20];

// Pre-converted, pre-permuted, pre-swizzled fp16 W: chunk of k XORed with (g'&7)
__device__ half whg[40 * 64];
// Pre-summed biases in permuted order
__device__ float bsumg[40];

__device__ __forceinline__ void fma2(unsigned long long& d,
                                     unsigned long long a,
                                     unsigned long long b) {
    asm("fma.rn.f32x2 %0, %1, %2, %0;" : "+l"(d) : "l"(a), "l"(b));
}
#define PACK2(d, lo, hi) \
    asm("mov.b64 %0, {%1, %2};" : "=l"(d) : "f"(lo), "f"(hi))
#define UNPACK2(lo, hi, s) \
    asm("mov.b64 {%0, %1}, %2;" : "=f"(lo), "=f"(hi) : "l"(s))

// ---------------------------------------------------------------------------
// K0: prep — W_ih to fp16, permute gate order, apply swizzle.
// ---------------------------------------------------------------------------
__global__ void prep_kernel(const float* __restrict__ W_ih,
                            const float* __restrict__ b_ih,
                            const float* __restrict__ b_hh)
{
    int e = blockIdx.x * 128 + threadIdx.x;
    if (e < 2560) {
        int g = e >> 6, k = e & 63;
        int gp = (g % 10) * 4 + g / 10;            // permuted column
        int kp = (((k >> 3) ^ (gp & 7)) << 3) | (k & 7);   // chunk XOR swizzle
        whg[gp * 64 + kp] = __float2half_rn(W_ih[e]);
    }
    if (e < 40) {
        int gp = (e % 10) * 4 + e / 10;
        bsumg[gp] = b_ih[e] + b_hh[e];
    }
}

// ---------------------------------------------------------------------------
// K1: xg = x · W_ihᵀ + bias via mma.sync m16n8k16, single-pass fp16.
// 256 threads (8 warps x 16 rows = 128 rows/block). fp16 epilogue.
// ---------------------------------------------------------------------------
__device__ __forceinline__ void mma16816(float* c, uint32_t a0, uint32_t a1,
                                         uint32_t a2, uint32_t a3,
                                         uint32_t b0, uint32_t b1)
{
    asm volatile(
        "mma.sync.aligned.m16n8k16.row.col.f32.f16.f16.f32 "
        "{%0,%1,%2,%3}, {%4,%5,%6,%7}, {%8,%9}, {%0,%1,%2,%3};"
        : "+f"(c[0]), "+f"(c[1]), "+f"(c[2]), "+f"(c[3])
        : "r"(a0), "r"(a1), "r"(a2), "r"(a3), "r"(b0), "r"(b1));
}

__global__ __launch_bounds__(256, 4)
void input_proj_mma(const float* __restrict__ x, int block0)
{
    __shared__ __align__(16) half Ah[128 * 64];     // 16 KB, swizzled
    __shared__ __align__(16) half Bsm[40 * 64];     // 5 KB
    __shared__ __align__(8)  float bsm[40];

    const int tid  = threadIdx.x;
    const int lane = tid & 31;
    const int wid  = tid >> 5;                     // 0..7, 16 rows each
    const size_t row0 = (size_t)(blockIdx.x + block0) * 128;

    // ---- stage x: fp32 -> fp16, chunk-XOR swizzle ----
    const float4* x4 = (const float4*)(x + row0 * IND);
    #pragma unroll
    for (int u = 0; u < 4; ++u) {
        int ch = tid + u * 256;                    // 1024 chunks = 128 rows x 8
        int r = ch >> 3, c = ch & 7;
        float4 v0 = __ldcs(&x4[r * 16 + c * 2]);
        float4 v1 = __ldcs(&x4[r * 16 + c * 2 + 1]);
        half h8[8];
        h8[0] = __float2half_rn(v0.x); h8[1] = __float2half_rn(v0.y);
        h8[2] = __float2half_rn(v0.z); h8[3] = __float2half_rn(v0.w);
        h8[4] = __float2half_rn(v1.x); h8[5] = __float2half_rn(v1.y);
        h8[6] = __float2half_rn(v1.z); h8[7] = __float2half_rn(v1.w);
        int off = r * 64 + ((c ^ (r & 7)) << 3);
        *(uint4*)&Ah[off] = *(const uint4*)h8;
    }
    // ---- stage W (already permuted+swizzled) + bias ----
    {
        const float4* wg4 = (const float4*)whg;    // 5120 B = 320 float4
        #pragma unroll
        for (int i = tid; i < 320; i += 256)
            ((float4*)Bsm)[i] = wg4[i];
        if (tid < 40)
            bsm[tid] = bsumg[tid];
    }
    __syncthreads();

    // ---- mma mainloop: 4 ks x 5 n = 20 MMAs per warp ----
    const int mrow0 = wid * 16;
    const int rgrp  = lane >> 2;                   // 0..7
    const int kq    = lane & 3;                    // 0..3
    const int ra    = mrow0 + rgrp;                // (ra&7)==rgrp

    float acc[5][4];
    #pragma unroll
    for (int n = 0; n < 5; ++n)
        #pragma unroll
        for (int i = 0; i < 4; ++i)
            acc[n][i] = 0.0f;

    #pragma unroll
    for (int ks = 0; ks < 4; ++ks) {
        const int ch0 = ((2 * ks)     ^ rgrp) * 8 + 2 * kq;
        const int ch1 = ((2 * ks + 1) ^ rgrp) * 8 + 2 * kq;

        uint32_t a0 = *(const uint32_t*)&Ah[ra * 64 + ch0];
        uint32_t a1 = *(const uint32_t*)&Ah[(ra + 8) * 64 + ch0];
        uint32_t a2 = *(const uint32_t*)&Ah[ra * 64 + ch1];
        uint32_t a3 = *(const uint32_t*)&Ah[(ra + 8) * 64 + ch1];

        #pragma unroll
        for (int n = 0; n < 5; ++n) {
            const int g = n * 8 + rgrp;            // (g&7)==rgrp -> same chunks
            uint32_t b0 = *(const uint32_t*)&Bsm[g * 64 + ch0];
            uint32_t b1 = *(const uint32_t*)&Bsm[g * 64 + ch1];
            mma16816(acc[n], a0, a1, a2, a3, b0, b1);
        }
    }

    // ---- epilogue: + bias (fp32), convert to fp16, direct STG.32 ----
    const size_t grA = row0 + mrow0 + rgrp;        // D rows rgrp, rgrp+8
    #pragma unroll
    for (int n = 0; n < 5; ++n) {
        const int cn = n * 8 + 2 * kq;             // even half-index
        float2 bp = *(const float2*)&bsm[cn];
        __half2 o0 = __floats2half2_rn(acc[n][0] + bp.x, acc[n][1] + bp.y);
        __half2 o1 = __floats2half2_rn(acc[n][2] + bp.x, acc[n][3] + bp.y);
        __stcs(&xg_h[grA * 20 + (cn >> 1)], o0);
        __stcs(&xg_h[(grA + 8) * 20 + (cn >> 1)], o1);
    }
}

// ---------------------------------------------------------------------------
// K2: recurrent scan. 3 batches/warp, shfl h-broadcast, fp16 xg stream.
// Gate-pair f32x2 accumulators: (i,f) and (g,o) packed — 20 FMA2 vs 40 FFMA.
// ---------------------------------------------------------------------------
__device__ __forceinline__ float sigm_mufu(float x) {
    // sigma(x) = 0.5*tanh(x/2) + 0.5  (1 MUFU)
    float t;
    asm("tanh.approx.f32 %0, %1;" : "=f"(t) : "f"(x * 0.5f));
    return fmaf(t, 0.5f, 0.5f);
}
__device__ __forceinline__ float tanh_mufu(float x) {
    float t;
    asm("tanh.approx.f32 %0, %1;" : "=f"(t) : "f"(x));
    return t;
}
__device__ __forceinline__ float tanh_fast(float x) {
    // precise-ish: 1 - 2/(e^{2x}+1)  (2 MUFU) — kept for the c->h output path
    return 1.0f - 2.0f * __fdividef(1.0f, 1.0f + __expf(2.0f * x));
}

#define K2_THREADS 64
#define K2_BATCH_PER_BLOCK 6

__global__ __launch_bounds__(K2_THREADS, 1)
void lstm_scan_kernel(const float* __restrict__ W_hh,
                      float* __restrict__ out)
{
    const int lane = threadIdx.x & 31;
    const int warp = threadIdx.x >> 5;
    int group = lane / 10;
    const bool active = (lane < 30);
    if (!active) group = 2;
    const int j = active ? (lane - group * 10) : 0;

    const int b = blockIdx.x * K2_BATCH_PER_BLOCK + warp * 3 + group;
    const bool valid = active && (b < BB);
    const int b_eff = valid ? b : 0;

    // gate-paired recurrent weights: wIF[k]=(wI[k],wF[k]), wGO[k]=(wG[k],wO[k])
    unsigned long long wIF[10], wGO[10];
    #pragma unroll
    for (int k = 0; k < 10; ++k) {
        PACK2(wIF[k], W_hh[(j)      * HH + k], W_hh[(j + 10) * HH + k]);
        PACK2(wGO[k], W_hh[(j + 20) * HH + k], W_hh[(j + 30) * HH + k]);
    }

    // fp16 xg stream: one uint2 (4 halves: i,f,g,o) per step, stride 10 uint2
    const uint2* xgp = (const uint2*)xg_h + (size_t)b_eff * TT * 10 + j;

    uint2 pf[8];
    #pragma unroll
    for (int d = 0; d < 8; ++d)
        pf[d] = __ldcs(&xgp[(size_t)d * 10]);

    float h = 0.0f, c = 0.0f;
    float* outp = out + (size_t)b_eff * TT * HH + j;
    const int srcbase = group * 10;

    for (int t = 0; t < TT; t += 8) {
        #pragma unroll
        for (int u = 0; u < 8; ++u) {
            uint2 xv = pf[u];
            int tn = t + u + 8;
            if (tn < TT)
                pf[u] = __ldcs(&xgp[(size_t)tn * 10]);

            float2 fIF = __half22float2(*(const __half2*)&xv.x);  // (i, f)
            float2 fGO = __half22float2(*(const __half2*)&xv.y);  // (g, o)
            unsigned long long aIF, aGO;
            PACK2(aIF, fIF.x, fIF.y);
            PACK2(aGO, fGO.x, fGO.y);

            #pragma unroll
            for (int k = 0; k < 10; ++k) {
                float hk = __shfl_sync(0xffffffffu, h, srcbase + k);
                unsigned long long hd;
                PACK2(hd, hk, hk);
                fma2(aIF, hd, wIF[k]);
                fma2(aGO, hd, wGO[k]);
            }
            float aI, aF, aG, aO;
            UNPACK2(aI, aF, aIF);
            UNPACK2(aG, aO, aGO);

            float ig = sigm_mufu(aI);
            float fg = sigm_mufu(aF);
            float gg = tanh_mufu(aG);
            float og = sigm_mufu(aO);
            c = fmaf(fg, c, ig * gg);
            h = og * tanh_fast(c);

            if (valid)
                __stcs(&outp[(size_t)(t + u) * HH], h);
        }
    }

    if (valid)
        out[(size_t)BB * TT * HH + (size_t)b * HH + j] = h;
}

// ---------------------------------------------------------------------------
extern "C" void kernel_launch(void* const* d_in, const int* in_sizes, int n_in,
                              void* d_out, int out_size)
{
    const float* x    = (const float*)d_in[0];
    const float* W_ih = (const float*)d_in[1];
    const float* W_hh = (const float*)d_in[2];
    const float* b_ih = (const float*)d_in[3];
    const float* b_hh = (const float*)d_in[4];
    float* out = (float*)d_out;

    prep_kernel<<<20, 128>>>(W_ih, b_ih, b_hh);

    // K1: 16384 CTAs of 128 rows, 4 chunks
    const int total_blocks = (BB * TT) / 128;      // 16384
    const int chunk = total_blocks / 4;            // 4096
    for (int i = 0; i < 4; ++i)
        input_proj_mma<<<chunk, 256>>>(x, i * chunk);

    int grid2 = (BB + K2_BATCH_PER_BLOCK - 1) / K2_BATCH_PER_BLOCK;  // 683
    lstm_scan_kernel<<<grid2, K2_THREADS>>>(W_hh, out);
}

// round 16
// speedup vs baseline: 1.6856x; 1.0174x over previous
#include <cuda_runtime.h>
#include <cuda_fp16.h>
#include <cstdint>

#define BB 4096
#define TT 512
#define IND 64
#define HH 10
#define TCH 128                  // timesteps per pipeline chunk (TT/4)

// 168 MB fp16 scratch: per bt, 20 half2 = 40 halves, idx = j*4+gate (i,f,g,o)
__device__ __half2 xg_h[(size_t)BB * TT * 20];

// Pre-converted, pre-permuted, pre-swizzled fp16 W: chunk of k XORed with (g'&7)
__device__ half whg[40 * 64];
__device__ float bsumg[40];

// persisted scan state between K2 quarters
__device__ float h_state[BB * HH];
__device__ float c_state[BB * HH];

__device__ __forceinline__ void fma2(unsigned long long& d,
                                     unsigned long long a,
                                     unsigned long long b) {
    asm("fma.rn.f32x2 %0, %1, %2, %0;" : "+l"(d) : "l"(a), "l"(b));
}
#define PACK2(d, lo, hi) \
    asm("mov.b64 %0, {%1, %2};" : "=l"(d) : "f"(lo), "f"(hi))
#define UNPACK2(lo, hi, s) \
    asm("mov.b64 {%0, %1}, %2;" : "=f"(lo), "=f"(hi) : "l"(s))

// ---------------------------------------------------------------------------
// K0: prep — W_ih to fp16, permute gate order, apply swizzle.
// ---------------------------------------------------------------------------
__global__ void prep_kernel(const float* __restrict__ W_ih,
                            const float* __restrict__ b_ih,
                            const float* __restrict__ b_hh)
{
    int e = blockIdx.x * 128 + threadIdx.x;
    if (e < 2560) {
        int g = e >> 6, k = e & 63;
        int gp = (g % 10) * 4 + g / 10;
        int kp = (((k >> 3) ^ (gp & 7)) << 3) | (k & 7);
        whg[gp * 64 + kp] = __float2half_rn(W_ih[e]);
    }
    if (e < 40) {
        int gp = (e % 10) * 4 + e / 10;
        bsumg[gp] = b_ih[e] + b_hh[e];
    }
}

// ---------------------------------------------------------------------------
// K1: time-chunked. Block = one batch x TCH contiguous timesteps (128 rows).
// mma.sync m16n8k16 single-pass fp16, fp16 epilogue.  grid = 4096 per chunk.
// ---------------------------------------------------------------------------
__device__ __forceinline__ void mma16816(float* c, uint32_t a0, uint32_t a1,
                                         uint32_t a2, uint32_t a3,
                                         uint32_t b0, uint32_t b1)
{
    asm volatile(
        "mma.sync.aligned.m16n8k16.row.col.f32.f16.f16.f32 "
        "{%0,%1,%2,%3}, {%4,%5,%6,%7}, {%8,%9}, {%0,%1,%2,%3};"
        : "+f"(c[0]), "+f"(c[1]), "+f"(c[2]), "+f"(c[3])
        : "r"(a0), "r"(a1), "r"(a2), "r"(a3), "r"(b0), "r"(b1));
}

__global__ __launch_bounds__(256, 4)
void input_proj_mma(const float* __restrict__ x, int t0)
{
    __shared__ __align__(16) half Ah[128 * 64];     // 16 KB, swizzled
    __shared__ __align__(16) half Bsm[40 * 64];     // 5 KB
    __shared__ __align__(8)  float bsm[40];

    const int tid  = threadIdx.x;
    const int lane = tid & 31;
    const int wid  = tid >> 5;                     // 0..7, 16 rows each
    const size_t row0 = (size_t)blockIdx.x * TT + t0;   // batch-major rows

    // ---- stage x: fp32 -> fp16, chunk-XOR swizzle ----
    const float4* x4 = (const float4*)(x + row0 * IND);
    #pragma unroll
    for (int u = 0; u < 4; ++u) {
        int ch = tid + u * 256;                    // 1024 chunks = 128 rows x 8
        int r = ch >> 3, c = ch & 7;
        float4 v0 = __ldcs(&x4[r * 16 + c * 2]);
        float4 v1 = __ldcs(&x4[r * 16 + c * 2 + 1]);
        half h8[8];
        h8[0] = __float2half_rn(v0.x); h8[1] = __float2half_rn(v0.y);
        h8[2] = __float2half_rn(v0.z); h8[3] = __float2half_rn(v0.w);
        h8[4] = __float2half_rn(v1.x); h8[5] = __float2half_rn(v1.y);
        h8[6] = __float2half_rn(v1.z); h8[7] = __float2half_rn(v1.w);
        int off = r * 64 + ((c ^ (r & 7)) << 3);
        *(uint4*)&Ah[off] = *(const uint4*)h8;
    }
    {
        const float4* wg4 = (const float4*)whg;    // 320 float4
        #pragma unroll
        for (int i = tid; i < 320; i += 256)
            ((float4*)Bsm)[i] = wg4[i];
        if (tid < 40)
            bsm[tid] = bsumg[tid];
    }
    __syncthreads();

    const int mrow0 = wid * 16;
    const int rgrp  = lane >> 2;
    const int kq    = lane & 3;
    const int ra    = mrow0 + rgrp;

    float acc[5][4];
    #pragma unroll
    for (int n = 0; n < 5; ++n)
        #pragma unroll
        for (int i = 0; i < 4; ++i)
            acc[n][i] = 0.0f;

    #pragma unroll
    for (int ks = 0; ks < 4; ++ks) {
        const int ch0 = ((2 * ks)     ^ rgrp) * 8 + 2 * kq;
        const int ch1 = ((2 * ks + 1) ^ rgrp) * 8 + 2 * kq;

        uint32_t a0 = *(const uint32_t*)&Ah[ra * 64 + ch0];
        uint32_t a1 = *(const uint32_t*)&Ah[(ra + 8) * 64 + ch0];
        uint32_t a2 = *(const uint32_t*)&Ah[ra * 64 + ch1];
        uint32_t a3 = *(const uint32_t*)&Ah[(ra + 8) * 64 + ch1];

        #pragma unroll
        for (int n = 0; n < 5; ++n) {
            const int g = n * 8 + rgrp;
            uint32_t b0 = *(const uint32_t*)&Bsm[g * 64 + ch0];
            uint32_t b1 = *(const uint32_t*)&Bsm[g * 64 + ch1];
            mma16816(acc[n], a0, a1, a2, a3, b0, b1);
        }
    }

    const size_t grA = row0 + mrow0 + rgrp;
    #pragma unroll
    for (int n = 0; n < 5; ++n) {
        const int cn = n * 8 + 2 * kq;
        float2 bp = *(const float2*)&bsm[cn];
        __half2 o0 = __floats2half2_rn(acc[n][0] + bp.x, acc[n][1] + bp.y);
        __half2 o1 = __floats2half2_rn(acc[n][2] + bp.x, acc[n][3] + bp.y);
        __stcs(&xg_h[grA * 20 + (cn >> 1)], o0);
        __stcs(&xg_h[(grA + 8) * 20 + (cn >> 1)], o1);
    }
}

// ---------------------------------------------------------------------------
// K2: resumable scan quarter t in [t0, t0+TCH). 3 batches/warp, shfl bcast,
// gate-pair f32x2, fp16 xg stream. h/c persisted in device state arrays.
// ---------------------------------------------------------------------------
__device__ __forceinline__ float sigm_mufu(float x) {
    float t;
    asm("tanh.approx.f32 %0, %1;" : "=f"(t) : "f"(x * 0.5f));
    return fmaf(t, 0.5f, 0.5f);
}
__device__ __forceinline__ float tanh_mufu(float x) {
    float t;
    asm("tanh.approx.f32 %0, %1;" : "=f"(t) : "f"(x));
    return t;
}
__device__ __forceinline__ float tanh_fast(float x) {
    return 1.0f - 2.0f * __fdividef(1.0f, 1.0f + __expf(2.0f * x));
}

#define K2_THREADS 64
#define K2_BATCH_PER_BLOCK 6

__global__ __launch_bounds__(K2_THREADS, 1)
void lstm_scan_kernel(const float* __restrict__ W_hh,
                      float* __restrict__ out, int t0)
{
    const int lane = threadIdx.x & 31;
    const int warp = threadIdx.x >> 5;
    int group = lane / 10;
    const bool active = (lane < 30);
    if (!active) group = 2;
    const int j = active ? (lane - group * 10) : 0;

    const int b = blockIdx.x * K2_BATCH_PER_BLOCK + warp * 3 + group;
    const bool valid = active && (b < BB);
    const int b_eff = valid ? b : 0;

    unsigned long long wIF[10], wGO[10];
    #pragma unroll
    for (int k = 0; k < 10; ++k) {
        PACK2(wIF[k], W_hh[(j)      * HH + k], W_hh[(j + 10) * HH + k]);
        PACK2(wGO[k], W_hh[(j + 20) * HH + k], W_hh[(j + 30) * HH + k]);
    }

    const uint2* xgp = (const uint2*)xg_h + (size_t)b_eff * TT * 10 + j;

    uint2 pf[8];
    #pragma unroll
    for (int d = 0; d < 8; ++d)
        pf[d] = __ldcs(&xgp[(size_t)(t0 + d) * 10]);

    float h = 0.0f, c = 0.0f;
    if (t0 > 0) {
        h = h_state[b_eff * HH + j];
        c = c_state[b_eff * HH + j];
    }
    float* outp = out + (size_t)b_eff * TT * HH + j;
    const int srcbase = group * 10;
    const int tend = t0 + TCH;

    for (int t = t0; t < tend; t += 8) {
        #pragma unroll
        for (int u = 0; u < 8; ++u) {
            uint2 xv = pf[u];
            int tn = t + u + 8;
            if (tn < tend)                         // stay inside this chunk
                pf[u] = __ldcs(&xgp[(size_t)tn * 10]);

            float2 fIF = __half22float2(*(const __half2*)&xv.x);
            float2 fGO = __half22float2(*(const __half2*)&xv.y);
            unsigned long long aIF, aGO;
            PACK2(aIF, fIF.x, fIF.y);
            PACK2(aGO, fGO.x, fGO.y);

            #pragma unroll
            for (int k = 0; k < 10; ++k) {
                float hk = __shfl_sync(0xffffffffu, h, srcbase + k);
                unsigned long long hd;
                PACK2(hd, hk, hk);
                fma2(aIF, hd, wIF[k]);
                fma2(aGO, hd, wGO[k]);
            }
            float aI, aF, aG, aO;
            UNPACK2(aI, aF, aIF);
            UNPACK2(aG, aO, aGO);

            float ig = sigm_mufu(aI);
            float fg = sigm_mufu(aF);
            float gg = tanh_mufu(aG);
            float og = sigm_mufu(aO);
            c = fmaf(fg, c, ig * gg);
            h = og * tanh_fast(c);

            if (valid)
                __stcs(&outp[(size_t)(t + u) * HH], h);
        }
    }

    if (valid) {
        if (tend >= TT) {
            out[(size_t)BB * TT * HH + (size_t)b * HH + j] = h;
        } else {
            h_state[b * HH + j] = h;
            c_state[b * HH + j] = c;
        }
    }
}

// ---------------------------------------------------------------------------
// Two-stream pipeline: K1 chunks (by time) on s2, K2 quarters on the default
// stream; event edges give K2_i -> K1_i dependency. Fork-join capturable.
// ---------------------------------------------------------------------------
extern "C" void kernel_launch(void* const* d_in, const int* in_sizes, int n_in,
                              void* d_out, int out_size)
{
    const float* x    = (const float*)d_in[0];
    const float* W_ih = (const float*)d_in[1];
    const float* W_hh = (const float*)d_in[2];
    const float* b_ih = (const float*)d_in[3];
    const float* b_hh = (const float*)d_in[4];
    float* out = (float*)d_out;

    static cudaStream_t s2 = nullptr;
    static cudaEvent_t evFork = nullptr, evK1[4];
    if (s2 == nullptr) {
        cudaStreamCreateWithFlags(&s2, cudaStreamNonBlocking);
        cudaEventCreateWithFlags(&evFork, cudaEventDisableTiming);
        for (int i = 0; i < 4; ++i)
            cudaEventCreateWithFlags(&evK1[i], cudaEventDisableTiming);
    }

    prep_kernel<<<20, 128>>>(W_ih, b_ih, b_hh);

    // fork: s2 inherits the prep dependency
    cudaEventRecord(evFork, 0);
    cudaStreamWaitEvent(s2, evFork, 0);

    // K1 chunks by time on s2 (grid = 4096 batches, 128 timesteps each)
    for (int i = 0; i < 4; ++i) {
        input_proj_mma<<<BB, 256, 0, s2>>>(x, i * TCH);
        cudaEventRecord(evK1[i], s2);
    }

    // K2 quarters on default stream, each gated on its K1 chunk
    int grid2 = (BB + K2_BATCH_PER_BLOCK - 1) / K2_BATCH_PER_BLOCK;  // 683
    for (int i = 0; i < 4; ++i) {
        cudaStreamWaitEvent(0, evK1[i], 0);
        lstm_scan_kernel<<<grid2, K2_THREADS>>>(W_hh, out, i * TCH);
    }
}